// round 11
// baseline (speedup 1.0000x reference)
#include <cuda_runtime.h>
#include <cuda_fp16.h>
#include <math.h>
#include <stdint.h>

#define BATCH 64
#define C1    64
#define C2    128
#define H0    224
#define W0    224
#define H1    112
#define W1    112
#define PIX   (H1*W1)
#define NT2   14            // conv2 tiles: 4 output rows each (56 rows / 4)

// conv1 output, channel-last fp16: [imgexp][h][w][ic]
__device__ unsigned short g_h1f[(size_t)2 * BATCH * PIX * C1];
// packed conv2 weights fp16 split: [e][tap][part(hi,mid)][oc=128][ic=64]
__device__ unsigned short g_w2pack[2 * 9 * 2 * 128 * 64];
// packed conv1 weights fp16 split: [part(hi,mid)][m=128 (t ocs then f ocs)][k=32]
__device__ unsigned short g_w1pack[2 * 128 * 32];
// pool partials: [imgexp][oc][tile]
__device__ float g_pool[2 * BATCH * C2 * NT2];
// per-sample routing flag
__device__ int g_use2[BATCH];

// mma.sync m16n8k16 fp16 (baseline PTX, works on plain sm_103 target)
#define MMA_F16(d, a, b) \
    asm volatile("mma.sync.aligned.m16n8k16.row.col.f32.f16.f16.f32 " \
        "{%0,%1,%2,%3}, {%4,%5,%6,%7}, {%8,%9}, {%0,%1,%2,%3};" \
        : "+f"((d)[0]), "+f"((d)[1]), "+f"((d)[2]), "+f"((d)[3]) \
        : "r"((a)[0]), "r"((a)[1]), "r"((a)[2]), "r"((a)[3]), \
          "r"((b)[0]), "r"((b)[1]))

// ldmatrix (baseline PTX sm_75+)
#define LDMX4(R, A) \
    asm volatile("ldmatrix.sync.aligned.m8n8.x4.shared.b16 {%0,%1,%2,%3}, [%4];" \
        : "=r"((R)[0]), "=r"((R)[1]), "=r"((R)[2]), "=r"((R)[3]) : "r"(A))
#define LDMX4B(R0, R1, A) \
    asm volatile("ldmatrix.sync.aligned.m8n8.x4.shared.b16 {%0,%1,%2,%3}, [%4];" \
        : "=r"((R0)[0]), "=r"((R0)[1]), "=r"((R1)[0]), "=r"((R1)[1]) : "r"(A))
#define LDMX2(R, A) \
    asm volatile("ldmatrix.sync.aligned.m8n8.x2.shared.b16 {%0,%1}, [%2];" \
        : "=r"((R)[0]), "=r"((R)[1]) : "r"(A))

__device__ __forceinline__ uint32_t pack_h2(float lo, float hi) {
    __half2 h = __floats2half2_rn(lo, hi);
    return *(uint32_t*)&h;
}

// ---------------------------------------------------------------------------
// weight pack (both convs)
// ---------------------------------------------------------------------------
__global__ void pack_weights_kernel(
    const float* __restrict__ tw2, const float* __restrict__ fw2,
    const float* __restrict__ tw1, const float* __restrict__ fw1)
{
    int idx = blockIdx.x * blockDim.x + threadIdx.x;
    if (idx < 2 * 9 * 128 * 64) {
        int e   = idx / 73728;
        int rem = idx - e * 73728;
        int tap = rem / 8192;
        int rem2 = rem - tap * 8192;
        int oc = rem2 >> 6, ic = rem2 & 63;
        float w = (e ? fw2 : tw2)[oc * 576 + ic * 9 + tap];
        __half h = __float2half_rn(w);
        __half m = __float2half_rn(w - __half2float(h));
        size_t base = (((size_t)(e * 9 + tap) * 2) * 128 + oc) * 64 + ic;
        g_w2pack[base]            = __half_as_ushort(h);
        g_w2pack[base + 128 * 64] = __half_as_ushort(m);
    } else {
        int j = idx - 2 * 9 * 128 * 64;
        if (j < 4096) {
            int m = j >> 5, k = j & 31;
            float w = 0.f;
            if (k < 27) w = (m < 64) ? tw1[m * 27 + k] : fw1[(m - 64) * 27 + k];
            __half h = __float2half_rn(w);
            __half mm = __float2half_rn(w - __half2float(h));
            g_w1pack[m * 32 + k]        = __half_as_ushort(h);
            g_w1pack[4096 + m * 32 + k] = __half_as_ushort(mm);
        }
    }
}

// ---------------------------------------------------------------------------
// conv1 via mma.sync fp16: CTA = (8x16 output tile, image b, BOTH experts).
// ---------------------------------------------------------------------------
#define SIN1_F    (3 * 17 * 36)
#define B_OFF1    7344
#define A_OFF1    (B_OFF1 + 128 * 80)
#define SMEM1_BYTES (A_OFF1 + 2 * 128 * 80)   // 38064 (sout 128x272 overlaps)
#define SOUT_STRIDE 136

__global__ __launch_bounds__(256) void conv1_mma_kernel(
    const float* __restrict__ x,
    const float* __restrict__ tb1, const float* __restrict__ fb1)
{
    extern __shared__ char smem[];
    float* sinp = (float*)smem;               // [3][17][36]
    const int tid = threadIdx.x;
    const int wid = tid >> 5, lane = tid & 31;
    const int wm = wid & 3;
    const int wn = wid >> 2;
    const int tile = blockIdx.x;              // 0..97
    const int b    = blockIdx.y;

    const int ty0 = (tile / 7) * 8;
    const int tx0 = (tile % 7) * 16;

    {
        const uint4* ws = (const uint4*)g_w1pack;
        #pragma unroll
        for (int ii = 0; ii < 4; ++ii) {
            int i = tid + ii * 256;
            int part = i >> 9, idx = i & 511;
            int row = idx >> 2, col = idx & 3;
            *(uint4*)(smem + A_OFF1 + part * 10240 + row * 80 + col * 16) = ws[i];
        }
    }
    {
        const int r0 = 2 * ty0, c0 = 2 * tx0;
        const float* xb = x + (size_t)b * 3 * H0 * W0;
        for (int i = tid; i < 3 * 17 * 33; i += 256) {
            int ic = i / 561;
            int rem = i - ic * 561;
            int r = rem / 33, c = rem - (rem / 33) * 33;
            int gr = r0 + r, gc = c0 + c;
            float v = 0.f;
            if (gr < H0 && gc < W0) v = xb[(size_t)ic * H0 * W0 + (size_t)gr * W0 + gc];
            sinp[(ic * 17 + r) * 36 + c] = v;
        }
    }
    __syncthreads();

    {
        const int n = tid >> 1;
        const int ohl = n >> 4, owl = n & 15;
        const int ib = 2 * ohl, jb = 2 * owl;
        char* brow = smem + B_OFF1 + n * 80;
        #define SIN1(icc, rr, cc) sinp[((icc) * 17 + (rr)) * 36 + (cc)]
        if ((tid & 1) == 0) {
            #pragma unroll
            for (int j = 0; j < 8; ++j) {
                const int k0 = 2 * j, k1 = k0 + 1;
                float v0 = SIN1(k0 / 9, ib + (k0 % 9) / 3, jb + k0 % 3);
                float v1 = SIN1(k1 / 9, ib + (k1 % 9) / 3, jb + k1 % 3);
                *(uint32_t*)(brow + k0 * 2) = pack_h2(v0, v1);
            }
        } else {
            #pragma unroll
            for (int j = 0; j < 8; ++j) {
                const int k0 = 16 + 2 * j, k1 = k0 + 1;
                float v0 = (k0 < 27) ? SIN1(k0 / 9, ib + (k0 % 9) / 3, jb + k0 % 3) : 0.f;
                float v1 = (k1 < 27) ? SIN1(k1 / 9, ib + (k1 % 9) / 3, jb + k1 % 3) : 0.f;
                *(uint32_t*)(brow + k0 * 2) = pack_h2(v0, v1);
            }
        }
        #undef SIN1
    }
    __syncthreads();

    float acc[2][8][4];
    #pragma unroll
    for (int mt = 0; mt < 2; ++mt)
        #pragma unroll
        for (int nt = 0; nt < 8; ++nt)
            #pragma unroll
            for (int j = 0; j < 4; ++j) acc[mt][nt][j] = 0.f;

    const uint32_t smem_u32 = (uint32_t)__cvta_generic_to_shared(smem);
    const int a_row = (lane & 7) + ((lane >> 3) & 1) * 8;
    const int a_col = (lane >> 4) * 16;
    uint32_t aoffH[2], aoffM[2];
    #pragma unroll
    for (int mt = 0; mt < 2; ++mt) {
        uint32_t r = (uint32_t)(A_OFF1 + (wm * 32 + mt * 16 + a_row) * 80 + a_col);
        aoffH[mt] = smem_u32 + r;
        aoffM[mt] = smem_u32 + r + 10240;
    }
    const int b_row = (lane & 7) + ((lane >> 4) & 1) * 8;
    const int b_col = ((lane >> 3) & 1) * 16;
    uint32_t boff[4];
    #pragma unroll
    for (int j = 0; j < 4; ++j)
        boff[j] = smem_u32 + (uint32_t)(B_OFF1 + (wn * 64 + j * 16 + b_row) * 80 + b_col);

    #pragma unroll
    for (int kk = 0; kk < 2; ++kk) {
        const uint32_t kb = (uint32_t)(kk * 32);
        uint32_t Ah[2][4], Am[2][4];
        #pragma unroll
        for (int mt = 0; mt < 2; ++mt) {
            LDMX4(Ah[mt], aoffH[mt] + kb);
            LDMX4(Am[mt], aoffM[mt] + kb);
        }
        uint32_t B[8][2];
        #pragma unroll
        for (int j = 0; j < 4; ++j)
            LDMX4B(B[2 * j], B[2 * j + 1], boff[j] + kb);
        #pragma unroll
        for (int mt = 0; mt < 2; ++mt)
            #pragma unroll
            for (int nt = 0; nt < 8; ++nt) {
                MMA_F16(acc[mt][nt], Ah[mt], B[nt]);
                MMA_F16(acc[mt][nt], Am[mt], B[nt]);
            }
    }
    __syncthreads();

    __half* sh = (__half*)smem;
    {
        const int r = lane >> 2, c2 = (lane & 3) * 2;
        #pragma unroll
        for (int mt = 0; mt < 2; ++mt) {
            const int m0 = wm * 32 + mt * 16 + r;
            const int m1 = m0 + 8;
            const float bias0 = (m0 < 64) ? tb1[m0] : fb1[m0 - 64];
            const float bias1 = (m1 < 64) ? tb1[m1] : fb1[m1 - 64];
            #pragma unroll
            for (int nt = 0; nt < 8; ++nt) {
                const int n0 = wn * 64 + nt * 8 + c2;
                sh[(n0)     * SOUT_STRIDE + m0] = __float2half_rn(fmaxf(acc[mt][nt][0] + bias0, 0.f));
                sh[(n0 + 1) * SOUT_STRIDE + m0] = __float2half_rn(fmaxf(acc[mt][nt][1] + bias0, 0.f));
                sh[(n0)     * SOUT_STRIDE + m1] = __float2half_rn(fmaxf(acc[mt][nt][2] + bias1, 0.f));
                sh[(n0 + 1) * SOUT_STRIDE + m1] = __float2half_rn(fmaxf(acc[mt][nt][3] + bias1, 0.f));
            }
        }
    }
    __syncthreads();

    #pragma unroll
    for (int ii = 0; ii < 8; ++ii) {
        int i = tid + ii * 256;
        int e2 = i >> 10, idx = i & 1023;
        int n = idx >> 3, q = idx & 7;
        int oh = ty0 + (n >> 4), ow = tx0 + (n & 15);
        uint4 v = *(const uint4*)(sh + n * SOUT_STRIDE + e2 * 64 + q * 8);
        size_t imgexp = (size_t)e2 * BATCH + b;
        *(uint4*)(g_h1f + imgexp * PIX * C1 + (size_t)(oh * W1 + ow) * C1 + q * 8) = v;
    }
}

// ---------------------------------------------------------------------------
// conv2 via mma.sync fp16: CTA = (imgexp, 4-output-row tile): M=128 x N=224
// 16 warps (4 M x 4 N), warp tile 32 x 56. fp16 split-A 2-combo.
// A single-buffered (36864B), B double-buffered (2 x 32256B). 2 CTAs/SM.
// ---------------------------------------------------------------------------
#define B_OFF2        36864
#define B_BUF_BYTES   32256                        // 224 * 144
#define SRED_OFF      (B_OFF2 + 2 * B_BUF_BYTES)   // 101376
#define SMEM2_BYTES   (SRED_OFF + 128 * 4 * 4)     // 103424

__global__ __launch_bounds__(512, 2) void conv2_mma_kernel(
    const float* __restrict__ tb2, const float* __restrict__ fb2)
{
    extern __shared__ char smem[];
    const int tid = threadIdx.x;
    const int wid = tid >> 5, lane = tid & 31;
    const int wm = wid & 3;          // M warp: 32*wm
    const int wn = wid >> 2;         // N warp: 56*wn (0..3)
    const int tileIdx = blockIdx.x;  // 0..13
    const int imgexp  = blockIdx.y;  // 0..127
    const int e = imgexp >> 6;
    const int oh0 = tileIdx * 4;

    const uint4* wsrc = (const uint4*)g_w2pack + (size_t)e * 9 * 2048;
    const uint4* src  = (const uint4*)g_h1f + (size_t)imgexp * PIX * 8;

    float acc[2][7][4];
    #pragma unroll
    for (int mt = 0; mt < 2; ++mt)
        #pragma unroll
        for (int nt = 0; nt < 7; ++nt)
            #pragma unroll
            for (int j = 0; j < 4; ++j) acc[mt][nt][j] = 0.f;

    auto stageA = [&](int t) {
        const uint4* ws = wsrc + t * 2048;
        #pragma unroll
        for (int ii = 0; ii < 4; ++ii) {
            int i = tid + ii * 512;              // 0..2047
            int part = i >> 10, idx = i & 1023;
            int row = idx >> 3, col = idx & 7;
            *(uint4*)(smem + part * 18432 + row * 144 + col * 16) = ws[i];
        }
    };
    auto stageB = [&](int t, int buf) {
        const int dy = t / 3, dx = t - (t / 3) * 3;
        char* bb = smem + B_OFF2 + buf * B_BUF_BYTES;
        #pragma unroll
        for (int ii = 0; ii < 4; ++ii) {
            int i = tid + ii * 512;              // 0..1791 used
            if (i < 1792) {
                int n = i >> 3, icq = i & 7;     // n: 0..223
                int ohl = n / 56;
                int ow = n - ohl * 56;
                int ih = 2 * (oh0 + ohl) + dy;
                int iw = 2 * ow + dx;
                uint4 v = make_uint4(0u, 0u, 0u, 0u);
                if (ih < H1 && iw < W1) v = src[(ih * W1 + iw) * 8 + icq];
                *(uint4*)(bb + n * 144 + icq * 16) = v;
            }
        }
    };

    stageA(0);
    stageB(0, 0);

    const uint32_t smem_u32 = (uint32_t)__cvta_generic_to_shared(smem);
    const int a_row = (lane & 7) + ((lane >> 3) & 1) * 8;
    const int a_col = (lane >> 4) * 16;
    uint32_t aoffH[2], aoffM[2];
    #pragma unroll
    for (int mt = 0; mt < 2; ++mt) {
        uint32_t r = (uint32_t)((wm * 32 + mt * 16 + a_row) * 144 + a_col);
        aoffH[mt] = smem_u32 + r;
        aoffM[mt] = smem_u32 + 18432 + r;
    }
    const int b_row = (lane & 7) + ((lane >> 4) & 1) * 8;
    const int b_col = ((lane >> 3) & 1) * 16;
    uint32_t boff[3];
    #pragma unroll
    for (int j = 0; j < 3; ++j)
        boff[j] = smem_u32 + B_OFF2 + (uint32_t)((wn * 56 + j * 16 + b_row) * 144 + b_col);
    const int b6_row = (lane & 7);
    const int b6_col = ((lane >> 3) & 1) * 16;
    const uint32_t boff6 = smem_u32 + B_OFF2 + (uint32_t)((wn * 56 + 48 + b6_row) * 144 + b6_col);

    __syncthreads();

    for (int t = 0; t < 9; ++t) {
        const int buf = t & 1;
        if (t < 8) stageB(t + 1, buf ^ 1);   // overlaps compute(t)

        const uint32_t bufoff = (uint32_t)(buf * B_BUF_BYTES);

        #pragma unroll
        for (int kk = 0; kk < 4; ++kk) {
            const uint32_t kb = (uint32_t)(kk * 32);
            uint32_t Ah[2][4], Am[2][4];
            #pragma unroll
            for (int mt = 0; mt < 2; ++mt) {
                LDMX4(Ah[mt], aoffH[mt] + kb);
                LDMX4(Am[mt], aoffM[mt] + kb);
            }
            uint32_t B[7][2];
            #pragma unroll
            for (int j = 0; j < 3; ++j)
                LDMX4B(B[2 * j], B[2 * j + 1], boff[j] + bufoff + kb);
            LDMX2(B[6], boff6 + bufoff + kb);

            #pragma unroll
            for (int mt = 0; mt < 2; ++mt)
                #pragma unroll
                for (int nt = 0; nt < 7; ++nt) {
                    MMA_F16(acc[mt][nt], Ah[mt], B[nt]);
                    MMA_F16(acc[mt][nt], Am[mt], B[nt]);
                }
        }
        __syncthreads();                     // compute(t) done; B(t+1) staged
        if (t < 8) {
            stageA(t + 1);                   // safe: all readers past A
            __syncthreads();
        }
    }

    // epilogue: bias + relu per element, deterministic pooled partial per oc
    float* sred = (float*)(smem + SRED_OFF);
    const float* b2 = e ? fb2 : tb2;
    const int mrow = lane >> 2;
    #pragma unroll
    for (int mt = 0; mt < 2; ++mt) {
        int m0 = wm * 32 + mt * 16 + mrow;
        float bias0 = b2[m0], bias1 = b2[m0 + 8];
        float s0 = 0.f, s1 = 0.f;
        #pragma unroll
        for (int nt = 0; nt < 7; ++nt) {
            s0 += fmaxf(acc[mt][nt][0] + bias0, 0.f) + fmaxf(acc[mt][nt][1] + bias0, 0.f);
            s1 += fmaxf(acc[mt][nt][2] + bias1, 0.f) + fmaxf(acc[mt][nt][3] + bias1, 0.f);
        }
        s0 += __shfl_xor_sync(0xffffffffu, s0, 1);
        s0 += __shfl_xor_sync(0xffffffffu, s0, 2);
        s1 += __shfl_xor_sync(0xffffffffu, s1, 1);
        s1 += __shfl_xor_sync(0xffffffffu, s1, 2);
        if ((lane & 3) == 0) {
            sred[m0 * 4 + wn] = s0;
            sred[(m0 + 8) * 4 + wn] = s1;
        }
    }
    __syncthreads();
    if (tid < 128)
        g_pool[((size_t)imgexp * C2 + tid) * NT2 + tileIdx] =
            (sred[tid * 4] + sred[tid * 4 + 1]) + (sred[tid * 4 + 2] + sred[tid * 4 + 3]);
}

// ---------------------------------------------------------------------------
// head: grid(64 samples) x 128 threads (one per oc). Deterministic tree reduce.
// ---------------------------------------------------------------------------
__global__ __launch_bounds__(128) void head_kernel(
    const float* __restrict__ twf, const float* __restrict__ tbf,
    const float* __restrict__ fwf, const float* __restrict__ fbf,
    float* __restrict__ out)
{
    __shared__ float s0[128], s1[128], s2[128], s3[128];
    const int b  = blockIdx.x;
    const int oc = threadIdx.x;
    const float inv = 1.f / 3136.f;

    const float* pt = &g_pool[((size_t)b * C2 + oc) * NT2];
    float gt = 0.f;
    #pragma unroll
    for (int k = 0; k < NT2; ++k) gt += pt[k];
    gt *= inv;
    const float* pf = &g_pool[((size_t)(BATCH + b) * C2 + oc) * NT2];
    float gf = 0.f;
    #pragma unroll
    for (int k = 0; k < NT2; ++k) gf += pf[k];
    gf *= inv;

    s0[oc] = gt * twf[oc * 2 + 0];
    s1[oc] = gt * twf[oc * 2 + 1];
    s2[oc] = gf * fwf[oc * 2 + 0];
    s3[oc] = gf * fwf[oc * 2 + 1];
    __syncthreads();

    #pragma unroll
    for (int stride = 64; stride > 0; stride >>= 1) {
        if (oc < stride) {
            s0[oc] += s0[oc + stride];
            s1[oc] += s1[oc + stride];
            s2[oc] += s2[oc + stride];
            s3[oc] += s3[oc + stride];
        }
        __syncthreads();
    }

    if (oc == 0) {
        float tl0 = s0[0] + tbf[0], tl1 = s1[0] + tbf[1];
        float fl0 = s2[0] + fbf[0], fl1 = s3[0] + fbf[1];
        float conf = 1.f / (1.f + expf(-fabsf(tl0 - tl1)));
        bool use2 = (conf <= 0.9f);
        out[b * 2 + 0] = use2 ? (0.7f * tl0 + 0.3f * fl0) : tl0;
        out[b * 2 + 1] = use2 ? (0.7f * tl1 + 0.3f * fl1) : tl1;
        g_use2[b] = use2 ? 1 : 0;
    }
}

__global__ void finalize_kernel(float* __restrict__ out, int out_size)
{
    __shared__ int sc[BATCH];
    const int t = threadIdx.x;
    sc[t] = g_use2[t];
    __syncthreads();
    #pragma unroll
    for (int stride = 32; stride > 0; stride >>= 1) {
        if (t < stride) sc[t] += sc[t + stride];
        __syncthreads();
    }
    if (t == 0 && out_size > 2 * BATCH)
        out[2 * BATCH] = (float)sc[0] / (float)BATCH;
}

// ---------------------------------------------------------------------------
extern "C" void kernel_launch(void* const* d_in, const int* in_sizes, int n_in,
                              void* d_out, int out_size)
{
    const float* x    = (const float*)d_in[0];
    const float* t_w1 = (const float*)d_in[1];
    const float* t_b1 = (const float*)d_in[2];
    const float* t_w2 = (const float*)d_in[3];
    const float* t_b2 = (const float*)d_in[4];
    const float* t_wf = (const float*)d_in[5];
    const float* t_bf = (const float*)d_in[6];
    const float* f_w1 = (const float*)d_in[7];
    const float* f_b1 = (const float*)d_in[8];
    const float* f_w2 = (const float*)d_in[9];
    const float* f_b2 = (const float*)d_in[10];
    const float* f_wf = (const float*)d_in[11];
    const float* f_bf = (const float*)d_in[12];
    float* out = (float*)d_out;

    cudaFuncSetAttribute(conv1_mma_kernel, cudaFuncAttributeMaxDynamicSharedMemorySize, SMEM1_BYTES);
    cudaFuncSetAttribute(conv2_mma_kernel, cudaFuncAttributeMaxDynamicSharedMemorySize, SMEM2_BYTES);

    pack_weights_kernel<<<149, 1024>>>(t_w2, f_w2, t_w1, f_w1);

    dim3 g1(98, BATCH);
    conv1_mma_kernel<<<g1, 256, SMEM1_BYTES>>>(x, t_b1, f_b1);

    dim3 g2(NT2, 2 * BATCH);
    conv2_mma_kernel<<<g2, 512, SMEM2_BYTES>>>(t_b2, f_b2);

    head_kernel<<<BATCH, 128>>>(t_wf, t_bf, f_wf, f_bf, out);
    finalize_kernel<<<1, BATCH>>>(out, out_size);
}

// round 13
// speedup vs baseline: 2.0598x; 2.0598x over previous
#include <cuda_runtime.h>
#include <cuda_fp16.h>
#include <math.h>
#include <stdint.h>

#define BATCH 64
#define C1    64
#define C2    128
#define H0    224
#define W0    224
#define H1    112
#define W1    112
#define PIX   (H1*W1)
#define NT2   28            // conv2 tiles: 2 output rows each (56 rows / 2)

// conv1 output, channel-last fp16: [imgexp][h][w][ic]
__device__ unsigned short g_h1f[(size_t)2 * BATCH * PIX * C1];
// packed conv2 weights fp16 split: [e][tap][part(hi,mid)][oc=128][ic=64]
__device__ unsigned short g_w2pack[2 * 9 * 2 * 128 * 64];
// packed conv1 weights fp16 split: [part(hi,mid)][m=128 (t ocs then f ocs)][k=32]
__device__ unsigned short g_w1pack[2 * 128 * 32];
// pool partials: [imgexp][oc][tile]
__device__ float g_pool[2 * BATCH * C2 * NT2];
// per-sample routing flag
__device__ int g_use2[BATCH];

// mma.sync m16n8k16 fp16 (baseline PTX, works on plain sm_103 target)
#define MMA_F16(d, a, b) \
    asm volatile("mma.sync.aligned.m16n8k16.row.col.f32.f16.f16.f32 " \
        "{%0,%1,%2,%3}, {%4,%5,%6,%7}, {%8,%9}, {%0,%1,%2,%3};" \
        : "+f"((d)[0]), "+f"((d)[1]), "+f"((d)[2]), "+f"((d)[3]) \
        : "r"((a)[0]), "r"((a)[1]), "r"((a)[2]), "r"((a)[3]), \
          "r"((b)[0]), "r"((b)[1]))

// ldmatrix (baseline PTX sm_75+)
#define LDMX4(R, A) \
    asm volatile("ldmatrix.sync.aligned.m8n8.x4.shared.b16 {%0,%1,%2,%3}, [%4];" \
        : "=r"((R)[0]), "=r"((R)[1]), "=r"((R)[2]), "=r"((R)[3]) : "r"(A))
#define LDMX4B(R0, R1, A) \
    asm volatile("ldmatrix.sync.aligned.m8n8.x4.shared.b16 {%0,%1,%2,%3}, [%4];" \
        : "=r"((R0)[0]), "=r"((R0)[1]), "=r"((R1)[0]), "=r"((R1)[1]) : "r"(A))
#define LDMX2(R, A) \
    asm volatile("ldmatrix.sync.aligned.m8n8.x2.shared.b16 {%0,%1}, [%2];" \
        : "=r"((R)[0]), "=r"((R)[1]) : "r"(A))

__device__ __forceinline__ uint32_t pack_h2(float lo, float hi) {
    __half2 h = __floats2half2_rn(lo, hi);
    return *(uint32_t*)&h;
}

// ---------------------------------------------------------------------------
// weight pack (both convs)
// ---------------------------------------------------------------------------
__global__ void pack_weights_kernel(
    const float* __restrict__ tw2, const float* __restrict__ fw2,
    const float* __restrict__ tw1, const float* __restrict__ fw1)
{
    int idx = blockIdx.x * blockDim.x + threadIdx.x;
    if (idx < 2 * 9 * 128 * 64) {
        int e   = idx / 73728;
        int rem = idx - e * 73728;
        int tap = rem / 8192;
        int rem2 = rem - tap * 8192;
        int oc = rem2 >> 6, ic = rem2 & 63;
        float w = (e ? fw2 : tw2)[oc * 576 + ic * 9 + tap];
        __half h = __float2half_rn(w);
        __half m = __float2half_rn(w - __half2float(h));
        size_t base = (((size_t)(e * 9 + tap) * 2) * 128 + oc) * 64 + ic;
        g_w2pack[base]            = __half_as_ushort(h);
        g_w2pack[base + 128 * 64] = __half_as_ushort(m);
    } else {
        int j = idx - 2 * 9 * 128 * 64;
        if (j < 4096) {
            int m = j >> 5, k = j & 31;
            float w = 0.f;
            if (k < 27) w = (m < 64) ? tw1[m * 27 + k] : fw1[(m - 64) * 27 + k];
            __half h = __float2half_rn(w);
            __half mm = __float2half_rn(w - __half2float(h));
            g_w1pack[m * 32 + k]        = __half_as_ushort(h);
            g_w1pack[4096 + m * 32 + k] = __half_as_ushort(mm);
        }
    }
}

// ---------------------------------------------------------------------------
// conv1 via mma.sync fp16: CTA = (8x16 output tile, image b, BOTH experts).
// ---------------------------------------------------------------------------
#define SIN1_F    (3 * 17 * 36)
#define B_OFF1    7344
#define A_OFF1    (B_OFF1 + 128 * 80)
#define SMEM1_BYTES (A_OFF1 + 2 * 128 * 80)   // 38064 (sout 128x272 overlaps)
#define SOUT_STRIDE 136

__global__ __launch_bounds__(256) void conv1_mma_kernel(
    const float* __restrict__ x,
    const float* __restrict__ tb1, const float* __restrict__ fb1)
{
    extern __shared__ char smem[];
    float* sinp = (float*)smem;               // [3][17][36]
    const int tid = threadIdx.x;
    const int wid = tid >> 5, lane = tid & 31;
    const int wm = wid & 3;
    const int wn = wid >> 2;
    const int tile = blockIdx.x;              // 0..97
    const int b    = blockIdx.y;

    const int ty0 = (tile / 7) * 8;
    const int tx0 = (tile % 7) * 16;

    {
        const uint4* ws = (const uint4*)g_w1pack;
        #pragma unroll
        for (int ii = 0; ii < 4; ++ii) {
            int i = tid + ii * 256;
            int part = i >> 9, idx = i & 511;
            int row = idx >> 2, col = idx & 3;
            *(uint4*)(smem + A_OFF1 + part * 10240 + row * 80 + col * 16) = ws[i];
        }
    }
    {
        const int r0 = 2 * ty0, c0 = 2 * tx0;
        const float* xb = x + (size_t)b * 3 * H0 * W0;
        for (int i = tid; i < 3 * 17 * 33; i += 256) {
            int ic = i / 561;
            int rem = i - ic * 561;
            int r = rem / 33, c = rem - (rem / 33) * 33;
            int gr = r0 + r, gc = c0 + c;
            float v = 0.f;
            if (gr < H0 && gc < W0) v = xb[(size_t)ic * H0 * W0 + (size_t)gr * W0 + gc];
            sinp[(ic * 17 + r) * 36 + c] = v;
        }
    }
    __syncthreads();

    {
        const int n = tid >> 1;
        const int ohl = n >> 4, owl = n & 15;
        const int ib = 2 * ohl, jb = 2 * owl;
        char* brow = smem + B_OFF1 + n * 80;
        #define SIN1(icc, rr, cc) sinp[((icc) * 17 + (rr)) * 36 + (cc)]
        if ((tid & 1) == 0) {
            #pragma unroll
            for (int j = 0; j < 8; ++j) {
                const int k0 = 2 * j, k1 = k0 + 1;
                float v0 = SIN1(k0 / 9, ib + (k0 % 9) / 3, jb + k0 % 3);
                float v1 = SIN1(k1 / 9, ib + (k1 % 9) / 3, jb + k1 % 3);
                *(uint32_t*)(brow + k0 * 2) = pack_h2(v0, v1);
            }
        } else {
            #pragma unroll
            for (int j = 0; j < 8; ++j) {
                const int k0 = 16 + 2 * j, k1 = k0 + 1;
                float v0 = (k0 < 27) ? SIN1(k0 / 9, ib + (k0 % 9) / 3, jb + k0 % 3) : 0.f;
                float v1 = (k1 < 27) ? SIN1(k1 / 9, ib + (k1 % 9) / 3, jb + k1 % 3) : 0.f;
                *(uint32_t*)(brow + k0 * 2) = pack_h2(v0, v1);
            }
        }
        #undef SIN1
    }
    __syncthreads();

    float acc[2][8][4];
    #pragma unroll
    for (int mt = 0; mt < 2; ++mt)
        #pragma unroll
        for (int nt = 0; nt < 8; ++nt)
            #pragma unroll
            for (int j = 0; j < 4; ++j) acc[mt][nt][j] = 0.f;

    const uint32_t smem_u32 = (uint32_t)__cvta_generic_to_shared(smem);
    const int a_row = (lane & 7) + ((lane >> 3) & 1) * 8;
    const int a_col = (lane >> 4) * 16;
    uint32_t aoffH[2], aoffM[2];
    #pragma unroll
    for (int mt = 0; mt < 2; ++mt) {
        uint32_t r = (uint32_t)(A_OFF1 + (wm * 32 + mt * 16 + a_row) * 80 + a_col);
        aoffH[mt] = smem_u32 + r;
        aoffM[mt] = smem_u32 + r + 10240;
    }
    const int b_row = (lane & 7) + ((lane >> 4) & 1) * 8;
    const int b_col = ((lane >> 3) & 1) * 16;
    uint32_t boff[4];
    #pragma unroll
    for (int j = 0; j < 4; ++j)
        boff[j] = smem_u32 + (uint32_t)(B_OFF1 + (wn * 64 + j * 16 + b_row) * 80 + b_col);

    #pragma unroll
    for (int kk = 0; kk < 2; ++kk) {
        const uint32_t kb = (uint32_t)(kk * 32);
        uint32_t Ah[2][4], Am[2][4];
        #pragma unroll
        for (int mt = 0; mt < 2; ++mt) {
            LDMX4(Ah[mt], aoffH[mt] + kb);
            LDMX4(Am[mt], aoffM[mt] + kb);
        }
        uint32_t B[8][2];
        #pragma unroll
        for (int j = 0; j < 4; ++j)
            LDMX4B(B[2 * j], B[2 * j + 1], boff[j] + kb);
        #pragma unroll
        for (int mt = 0; mt < 2; ++mt)
            #pragma unroll
            for (int nt = 0; nt < 8; ++nt) {
                MMA_F16(acc[mt][nt], Ah[mt], B[nt]);
                MMA_F16(acc[mt][nt], Am[mt], B[nt]);
            }
    }
    __syncthreads();

    __half* sh = (__half*)smem;
    {
        const int r = lane >> 2, c2 = (lane & 3) * 2;
        #pragma unroll
        for (int mt = 0; mt < 2; ++mt) {
            const int m0 = wm * 32 + mt * 16 + r;
            const int m1 = m0 + 8;
            const float bias0 = (m0 < 64) ? tb1[m0] : fb1[m0 - 64];
            const float bias1 = (m1 < 64) ? tb1[m1] : fb1[m1 - 64];
            #pragma unroll
            for (int nt = 0; nt < 8; ++nt) {
                const int n0 = wn * 64 + nt * 8 + c2;
                sh[(n0)     * SOUT_STRIDE + m0] = __float2half_rn(fmaxf(acc[mt][nt][0] + bias0, 0.f));
                sh[(n0 + 1) * SOUT_STRIDE + m0] = __float2half_rn(fmaxf(acc[mt][nt][1] + bias0, 0.f));
                sh[(n0)     * SOUT_STRIDE + m1] = __float2half_rn(fmaxf(acc[mt][nt][2] + bias1, 0.f));
                sh[(n0 + 1) * SOUT_STRIDE + m1] = __float2half_rn(fmaxf(acc[mt][nt][3] + bias1, 0.f));
            }
        }
    }
    __syncthreads();

    #pragma unroll
    for (int ii = 0; ii < 8; ++ii) {
        int i = tid + ii * 256;
        int e2 = i >> 10, idx = i & 1023;
        int n = idx >> 3, q = idx & 7;
        int oh = ty0 + (n >> 4), ow = tx0 + (n & 15);
        uint4 v = *(const uint4*)(sh + n * SOUT_STRIDE + e2 * 64 + q * 8);
        size_t imgexp = (size_t)e2 * BATCH + b;
        *(uint4*)(g_h1f + imgexp * PIX * C1 + (size_t)(oh * W1 + ow) * C1 + q * 8) = v;
    }
}

// ---------------------------------------------------------------------------
// conv2 via mma.sync fp16: CTA = (imgexp, 2-output-row tile): M=128 x N=112
// 8 warps (4 M x 2 N), warp tile 32 x 56. fp16 split-A 2-combo.
// BOTH A and B double-buffered -> single __syncthreads per tap, no exposed
// staging. smem 107008 B; 2 CTAs/SM (214KB < 228KB carveout, 256 thr, <=128 regs).
// ---------------------------------------------------------------------------
#define A_BUF_BYTES   36864                        // per buffer: hi@0, mid@18432
#define B_OFF2        73728                        // 2 A buffers
#define B_BUF_BYTES   16128                        // 112 * 144
#define SRED_OFF      (B_OFF2 + 2 * B_BUF_BYTES)   // 105984
#define SMEM2_BYTES   (SRED_OFF + 128 * 2 * 4)     // 107008

__global__ __launch_bounds__(256, 2) void conv2_mma_kernel(
    const float* __restrict__ tb2, const float* __restrict__ fb2)
{
    extern __shared__ char smem[];
    const int tid = threadIdx.x;
    const int wid = tid >> 5, lane = tid & 31;
    const int wm = wid & 3;          // M warp: 32*wm
    const int wn = wid >> 2;         // N warp: 56*wn
    const int tileIdx = blockIdx.x;  // 0..27
    const int imgexp  = blockIdx.y;  // 0..127
    const int e = imgexp >> 6;
    const int oh0 = tileIdx * 2;

    const uint4* wsrc = (const uint4*)g_w2pack + (size_t)e * 9 * 2048;
    const uint4* src  = (const uint4*)g_h1f + (size_t)imgexp * PIX * 8;

    float acc[2][7][4];
    #pragma unroll
    for (int mt = 0; mt < 2; ++mt)
        #pragma unroll
        for (int nt = 0; nt < 7; ++nt)
            #pragma unroll
            for (int j = 0; j < 4; ++j) acc[mt][nt][j] = 0.f;

    auto stageA = [&](int t, int buf) {
        const uint4* ws = wsrc + t * 2048;
        char* ab = smem + buf * A_BUF_BYTES;
        #pragma unroll
        for (int ii = 0; ii < 8; ++ii) {
            int i = tid + ii * 256;              // 0..2047
            int part = i >> 10, idx = i & 1023;
            int row = idx >> 3, col = idx & 7;
            *(uint4*)(ab + part * 18432 + row * 144 + col * 16) = ws[i];
        }
    };
    auto stageB = [&](int t, int buf) {
        const int dy = t / 3, dx = t - (t / 3) * 3;
        char* bb = smem + B_OFF2 + buf * B_BUF_BYTES;
        #pragma unroll
        for (int ii = 0; ii < 4; ++ii) {
            int i = tid + ii * 256;              // 0..895 used
            if (i < 896) {
                int n = i >> 3, icq = i & 7;
                int ohl = (n >= 56) ? 1 : 0;
                int ow = n - ohl * 56;
                int ih = 2 * (oh0 + ohl) + dy;
                int iw = 2 * ow + dx;
                uint4 v = make_uint4(0u, 0u, 0u, 0u);
                if (ih < H1 && iw < W1) v = src[(ih * W1 + iw) * 8 + icq];
                *(uint4*)(bb + n * 144 + icq * 16) = v;
            }
        }
    };

    stageA(0, 0);
    stageB(0, 0);

    const uint32_t smem_u32 = (uint32_t)__cvta_generic_to_shared(smem);
    const int a_row = (lane & 7) + ((lane >> 3) & 1) * 8;
    const int a_col = (lane >> 4) * 16;
    uint32_t aoffH[2], aoffM[2];
    #pragma unroll
    for (int mt = 0; mt < 2; ++mt) {
        uint32_t r = (uint32_t)((wm * 32 + mt * 16 + a_row) * 144 + a_col);
        aoffH[mt] = smem_u32 + r;
        aoffM[mt] = smem_u32 + 18432 + r;
    }
    const int b_row = (lane & 7) + ((lane >> 4) & 1) * 8;
    const int b_col = ((lane >> 3) & 1) * 16;
    uint32_t boff[3];
    #pragma unroll
    for (int j = 0; j < 3; ++j)
        boff[j] = smem_u32 + B_OFF2 + (uint32_t)((wn * 56 + j * 16 + b_row) * 144 + b_col);
    const int b6_row = (lane & 7);
    const int b6_col = ((lane >> 3) & 1) * 16;
    const uint32_t boff6 = smem_u32 + B_OFF2 + (uint32_t)((wn * 56 + 48 + b6_row) * 144 + b6_col);

    __syncthreads();

    for (int t = 0; t < 9; ++t) {
        const int buf = t & 1;
        // stage everything for t+1 into the other buffer; overlaps compute(t)
        if (t < 8) { stageA(t + 1, buf ^ 1); stageB(t + 1, buf ^ 1); }

        const uint32_t abufoff = (uint32_t)(buf * A_BUF_BYTES);
        const uint32_t bbufoff = (uint32_t)(buf * B_BUF_BYTES);

        #pragma unroll
        for (int kk = 0; kk < 4; ++kk) {
            const uint32_t kb = (uint32_t)(kk * 32);
            uint32_t Ah[2][4], Am[2][4];
            #pragma unroll
            for (int mt = 0; mt < 2; ++mt) {
                LDMX4(Ah[mt], aoffH[mt] + abufoff + kb);
                LDMX4(Am[mt], aoffM[mt] + abufoff + kb);
            }
            uint32_t B[7][2];
            #pragma unroll
            for (int j = 0; j < 3; ++j)
                LDMX4B(B[2 * j], B[2 * j + 1], boff[j] + bbufoff + kb);
            LDMX2(B[6], boff6 + bbufoff + kb);

            #pragma unroll
            for (int mt = 0; mt < 2; ++mt)
                #pragma unroll
                for (int nt = 0; nt < 7; ++nt) {
                    MMA_F16(acc[mt][nt], Ah[mt], B[nt]);
                    MMA_F16(acc[mt][nt], Am[mt], B[nt]);
                }
        }
        // one sync per tap: compute(t) done AND stage(t+1) visible;
        // next iteration stages into buf (t+2) only after this barrier.
        __syncthreads();
    }

    // epilogue: bias + relu per element, deterministic pooled partial per oc
    float* sred = (float*)(smem + SRED_OFF);
    const float* b2 = e ? fb2 : tb2;
    const int mrow = lane >> 2;
    #pragma unroll
    for (int mt = 0; mt < 2; ++mt) {
        int m0 = wm * 32 + mt * 16 + mrow;
        float bias0 = b2[m0], bias1 = b2[m0 + 8];
        float s0 = 0.f, s1 = 0.f;
        #pragma unroll
        for (int nt = 0; nt < 7; ++nt) {
            s0 += fmaxf(acc[mt][nt][0] + bias0, 0.f) + fmaxf(acc[mt][nt][1] + bias0, 0.f);
            s1 += fmaxf(acc[mt][nt][2] + bias1, 0.f) + fmaxf(acc[mt][nt][3] + bias1, 0.f);
        }
        s0 += __shfl_xor_sync(0xffffffffu, s0, 1);
        s0 += __shfl_xor_sync(0xffffffffu, s0, 2);
        s1 += __shfl_xor_sync(0xffffffffu, s1, 1);
        s1 += __shfl_xor_sync(0xffffffffu, s1, 2);
        if ((lane & 3) == 0) {
            sred[m0 * 2 + wn] = s0;
            sred[(m0 + 8) * 2 + wn] = s1;
        }
    }
    __syncthreads();
    if (tid < 128)
        g_pool[((size_t)imgexp * C2 + tid) * NT2 + tileIdx] = sred[tid * 2] + sred[tid * 2 + 1];
}

// ---------------------------------------------------------------------------
// head: grid(64 samples) x 128 threads (one per oc). Deterministic tree reduce.
// ---------------------------------------------------------------------------
__global__ __launch_bounds__(128) void head_kernel(
    const float* __restrict__ twf, const float* __restrict__ tbf,
    const float* __restrict__ fwf, const float* __restrict__ fbf,
    float* __restrict__ out)
{
    __shared__ float s0[128], s1[128], s2[128], s3[128];
    const int b  = blockIdx.x;
    const int oc = threadIdx.x;
    const float inv = 1.f / 3136.f;

    const float* pt = &g_pool[((size_t)b * C2 + oc) * NT2];
    float gt = 0.f;
    #pragma unroll
    for (int k = 0; k < NT2; ++k) gt += pt[k];
    gt *= inv;
    const float* pf = &g_pool[((size_t)(BATCH + b) * C2 + oc) * NT2];
    float gf = 0.f;
    #pragma unroll
    for (int k = 0; k < NT2; ++k) gf += pf[k];
    gf *= inv;

    s0[oc] = gt * twf[oc * 2 + 0];
    s1[oc] = gt * twf[oc * 2 + 1];
    s2[oc] = gf * fwf[oc * 2 + 0];
    s3[oc] = gf * fwf[oc * 2 + 1];
    __syncthreads();

    #pragma unroll
    for (int stride = 64; stride > 0; stride >>= 1) {
        if (oc < stride) {
            s0[oc] += s0[oc + stride];
            s1[oc] += s1[oc + stride];
            s2[oc] += s2[oc + stride];
            s3[oc] += s3[oc + stride];
        }
        __syncthreads();
    }

    if (oc == 0) {
        float tl0 = s0[0] + tbf[0], tl1 = s1[0] + tbf[1];
        float fl0 = s2[0] + fbf[0], fl1 = s3[0] + fbf[1];
        float conf = 1.f / (1.f + expf(-fabsf(tl0 - tl1)));
        bool use2 = (conf <= 0.9f);
        out[b * 2 + 0] = use2 ? (0.7f * tl0 + 0.3f * fl0) : tl0;
        out[b * 2 + 1] = use2 ? (0.7f * tl1 + 0.3f * fl1) : tl1;
        g_use2[b] = use2 ? 1 : 0;
    }
}

__global__ void finalize_kernel(float* __restrict__ out, int out_size)
{
    __shared__ int sc[BATCH];
    const int t = threadIdx.x;
    sc[t] = g_use2[t];
    __syncthreads();
    #pragma unroll
    for (int stride = 32; stride > 0; stride >>= 1) {
        if (t < stride) sc[t] += sc[t + stride];
        __syncthreads();
    }
    if (t == 0 && out_size > 2 * BATCH)
        out[2 * BATCH] = (float)sc[0] / (float)BATCH;
}

// ---------------------------------------------------------------------------
extern "C" void kernel_launch(void* const* d_in, const int* in_sizes, int n_in,
                              void* d_out, int out_size)
{
    const float* x    = (const float*)d_in[0];
    const float* t_w1 = (const float*)d_in[1];
    const float* t_b1 = (const float*)d_in[2];
    const float* t_w2 = (const float*)d_in[3];
    const float* t_b2 = (const float*)d_in[4];
    const float* t_wf = (const float*)d_in[5];
    const float* t_bf = (const float*)d_in[6];
    const float* f_w1 = (const float*)d_in[7];
    const float* f_b1 = (const float*)d_in[8];
    const float* f_w2 = (const float*)d_in[9];
    const float* f_b2 = (const float*)d_in[10];
    const float* f_wf = (const float*)d_in[11];
    const float* f_bf = (const float*)d_in[12];
    float* out = (float*)d_out;

    cudaFuncSetAttribute(conv1_mma_kernel, cudaFuncAttributeMaxDynamicSharedMemorySize, SMEM1_BYTES);
    cudaFuncSetAttribute(conv2_mma_kernel, cudaFuncAttributeMaxDynamicSharedMemorySize, SMEM2_BYTES);

    pack_weights_kernel<<<149, 1024>>>(t_w2, f_w2, t_w1, f_w1);

    dim3 g1(98, BATCH);
    conv1_mma_kernel<<<g1, 256, SMEM1_BYTES>>>(x, t_b1, f_b1);

    dim3 g2(NT2, 2 * BATCH);
    conv2_mma_kernel<<<g2, 256, SMEM2_BYTES>>>(t_b2, f_b2);

    head_kernel<<<BATCH, 128>>>(t_wf, t_bf, f_wf, f_bf, out);
    finalize_kernel<<<1, BATCH>>>(out, out_size);
}